// round 17
// baseline (speedup 1.0000x reference)
#include <cuda_runtime.h>
#include <cuda_fp16.h>
#include <cstdint>

#define BATCH   4
#define TSEQ    4096
#define CDIM    512
#define HDIM    64
#define BT_TOTAL (BATCH * TSEQ)   // 16384
#define QTILE   128
#define KTILE   32
#define NSPLIT  4
#define KEYS_PER_SPLIT (TSEQ / NSPLIT)     // 1024
#define NT      (KEYS_PER_SPLIT / KTILE)   // 32

#define KVSTRU2 20   // K/V/W row stride in uint2 (16 used)
#define PSTRU2  12   // P row stride in uint2 (8 used)
#define XSTR    36   // xs row stride (floats)

typedef unsigned int uint32;

// ---- fp16 helpers ----
__device__ __forceinline__ uint32 pkh2(float a, float b) {
    __half2 h = __floats2half2_rn(a, b);
    return *reinterpret_cast<uint32*>(&h);
}
__device__ __forceinline__ float f16lo(float a) {
    return a - __half2float(__float2half_rn(a));
}
__device__ __forceinline__ void mma_f16(
    float& c0, float& c1, float& c2, float& c3,
    uint32 a0, uint32 a1, uint32 a2, uint32 a3,
    uint32 b0, uint32 b1)
{
    asm("mma.sync.aligned.m16n8k16.row.col.f32.f16.f16.f32 "
        "{%0,%1,%2,%3},{%4,%5,%6,%7},{%8,%9},{%0,%1,%2,%3};"
        : "+f"(c0), "+f"(c1), "+f"(c2), "+f"(c3)
        : "r"(a0), "r"(a1), "r"(a2), "r"(a3), "r"(b0), "r"(b1));
}

// Scratch (static device arrays per allocation rules).
__device__ float g_q[BT_TOTAL * HDIM];
__device__ float g_k[BT_TOTAL * HDIM];
__device__ float g_v[BT_TOTAL * HDIM];
__device__ uint32 g_wh[3][HDIM][CDIM / 2];   // W^T hi, half2-packed along k
__device__ uint32 g_wl[3][HDIM][CDIM / 2];   // W^T lo
// split-KV partials
__device__ float g_pacc[NSPLIT][BT_TOTAL][HDIM];
__device__ float g_pm[NSPLIT][BT_TOTAL];
__device__ float g_pl[NSPLIT][BT_TOTAL];

// ---------------------------------------------------------------------------
// Transpose + hi/lo split W [512][64] -> g_wh/g_wl [64][256] half2.
// ---------------------------------------------------------------------------
__global__ __launch_bounds__(256) void transpose_w_kernel(
    const float* __restrict__ Wq,
    const float* __restrict__ Wk,
    const float* __restrict__ Wv)
{
    const int mat = blockIdx.y;
    const float* __restrict__ W = (mat == 0) ? Wq : (mat == 1) ? Wk : Wv;
    const int idx = blockIdx.x * 256 + threadIdx.x;   // 0..16383
    const int k2  = idx & (CDIM / 2 - 1);
    const int n   = idx >> 8;
    const float w0 = W[(2 * k2) * HDIM + n];
    const float w1 = W[(2 * k2 + 1) * HDIM + n];
    g_wh[mat][n][k2] = pkh2(w0, w1);
    g_wl[mat][n][k2] = pkh2(f16lo(w0), f16lo(w1));
}

// ---------------------------------------------------------------------------
// Projection GEMM on fp16 HMMA m16n8k16, 3-term split (unchanged from R15).
// ---------------------------------------------------------------------------
__global__ __launch_bounds__(128) void proj_mma_kernel(const float* __restrict__ x)
{
    __shared__ float xs[128 * XSTR];
    __shared__ uint2 Whs[HDIM * KVSTRU2];
    __shared__ uint2 Wls[HDIM * KVSTRU2];

    const int mat  = blockIdx.y;
    float* __restrict__ out = (mat == 0) ? g_q : (mat == 1) ? g_k : g_v;
    const int row0 = blockIdx.x * 128;
    const int tid  = threadIdx.x;
    const int w    = tid >> 5;
    const int ln   = tid & 31;
    const int g    = ln >> 2;
    const int tg   = ln & 3;

    float o[2][8][4];
    #pragma unroll
    for (int m = 0; m < 2; m++)
        #pragma unroll
        for (int n = 0; n < 8; n++)
            #pragma unroll
            for (int i = 0; i < 4; i++) o[m][n][i] = 0.0f;

    #pragma unroll 1
    for (int k0 = 0; k0 < CDIM; k0 += 32) {
        __syncthreads();
        #pragma unroll
        for (int p = 0; p < 8; p++) {
            const int task = p * 128 + tid;
            const int r    = task >> 3;
            const int cg   = task & 7;
            float4 v = *reinterpret_cast<const float4*>(
                &x[(long)(row0 + r) * CDIM + k0 + cg * 4]);
            *reinterpret_cast<float4*>(&xs[r * XSTR + cg * 4]) = v;
        }
        #pragma unroll
        for (int p = 0; p < 4; p++) {
            const int task = p * 128 + tid;
            const int n    = task >> 3;
            const int j    = task & 7;
            const int kap  = j >> 2;
            const int t2   = j & 3;
            const int src  = (k0 >> 1) + kap * 8 + t2;
            const int dst  = n * KVSTRU2 + kap * 4 + t2;
            Whs[dst] = make_uint2(g_wh[mat][n][src], g_wh[mat][n][src + 4]);
            Wls[dst] = make_uint2(g_wl[mat][n][src], g_wl[mat][n][src + 4]);
        }
        __syncthreads();

        #pragma unroll
        for (int kap = 0; kap < 2; kap++) {
            uint4 ah[2], al[2];
            #pragma unroll
            for (int m = 0; m < 2; m++) {
                const int r = w * 32 + m * 16 + g;
                const int c = kap * 16 + 2 * tg;
                float2 a00 = *reinterpret_cast<const float2*>(&xs[r * XSTR + c]);
                float2 a10 = *reinterpret_cast<const float2*>(&xs[(r + 8) * XSTR + c]);
                float2 a01 = *reinterpret_cast<const float2*>(&xs[r * XSTR + c + 8]);
                float2 a11 = *reinterpret_cast<const float2*>(&xs[(r + 8) * XSTR + c + 8]);
                ah[m] = make_uint4(pkh2(a00.x, a00.y), pkh2(a10.x, a10.y),
                                   pkh2(a01.x, a01.y), pkh2(a11.x, a11.y));
                al[m] = make_uint4(pkh2(f16lo(a00.x), f16lo(a00.y)),
                                   pkh2(f16lo(a10.x), f16lo(a10.y)),
                                   pkh2(f16lo(a01.x), f16lo(a01.y)),
                                   pkh2(f16lo(a11.x), f16lo(a11.y)));
            }
            #pragma unroll
            for (int n = 0; n < 8; n++) {
                const int widx = (n * 8 + g) * KVSTRU2 + kap * 4 + tg;
                uint2 wh = Whs[widx];
                uint2 wl = Wls[widx];
                #pragma unroll
                for (int m = 0; m < 2; m++) {
                    mma_f16(o[m][n][0], o[m][n][1], o[m][n][2], o[m][n][3],
                            ah[m].x, ah[m].y, ah[m].z, ah[m].w, wh.x, wh.y);
                    mma_f16(o[m][n][0], o[m][n][1], o[m][n][2], o[m][n][3],
                            al[m].x, al[m].y, al[m].z, al[m].w, wh.x, wh.y);
                    mma_f16(o[m][n][0], o[m][n][1], o[m][n][2], o[m][n][3],
                            ah[m].x, ah[m].y, ah[m].z, ah[m].w, wl.x, wl.y);
                }
            }
        }
    }

    const float scale = (mat == 0) ? 8.0f : 1.0f;
    #pragma unroll
    for (int m = 0; m < 2; m++) {
        const long rowA = (long)(row0 + w * 32 + m * 16 + g);
        const long rowB = rowA + 8;
        #pragma unroll
        for (int n = 0; n < 8; n++) {
            const int c = n * 8 + 2 * tg;
            *reinterpret_cast<float2*>(&out[rowA * HDIM + c]) =
                make_float2(o[m][n][0] * scale, o[m][n][1] * scale);
            *reinterpret_cast<float2*>(&out[rowB * HDIM + c]) =
                make_float2(o[m][n][2] * scale, o[m][n][3] * scale);
        }
    }
}

// ---------------------------------------------------------------------------
// Flash attention on fp16 HMMA m16n8k16. QK = 3-term fp16 split, PV = 1x.
// Occupancy build: __launch_bounds__(128,3) + 64 KB smem -> 3 CTAs/SM
// (3 warps/SMSP). K register-prefetched; V loaded at staging (L2-resident,
// latency hidden by warp rotation). grid (TSEQ/128, BATCH, NSPLIT=4).
// ---------------------------------------------------------------------------
__global__ __launch_bounds__(128, 3) void attn_mma_kernel()
{
    extern __shared__ uint4 smu[];
    uint4* QAh = smu;                                      // 1024 uint4
    uint4* QAl = smu + 1024;                               // 1024 uint4
    uint2* Kh  = reinterpret_cast<uint2*>(smu + 2048);     // 640 uint2
    uint2* Kl  = Kh + 640;                                 // 640
    uint2* Vh  = Kl + 640;                                 // 1280
    uint2* P2h = Vh + 1280;                                // 1536

    const int b     = blockIdx.y;
    const int split = blockIdx.z;
    const int q0    = blockIdx.x * QTILE;
    const int tid   = threadIdx.x;
    const int w     = tid >> 5;
    const int ln    = tid & 31;
    const int g     = ln >> 2;
    const int tg    = ln & 3;

    const float* __restrict__ kb = &g_k[(long)b * TSEQ * HDIM];
    const float* __restrict__ vb = &g_v[(long)b * TSEQ * HDIM];

    const int kkey0 = tid >> 3, kc0 = tid & 7;
    const int kkey1 = (128 + tid) >> 3, kc1 = (128 + tid) & 7;
    const int vk2 = tid >> 3;
    const int vh8 = (tid & 7) * 8;

    // ---- stage Q ----
    #pragma unroll
    for (int i = 0; i < 8; i++) {
        const int e   = tid * 8 + i;
        const int mb  = e >> 7;
        const int kap = (e >> 5) & 3;
        const int gg  = (e >> 2) & 7;
        const int tt  = e & 3;
        const int r   = (mb >> 1) * 32 + (mb & 1) * 16 + gg;
        const int c   = kap * 16 + 2 * tt;
        const float* r0p = &g_q[((long)b * TSEQ + q0 + r) * HDIM];
        const float* r1p = &g_q[((long)b * TSEQ + q0 + r + 8) * HDIM];
        float2 q00 = *reinterpret_cast<const float2*>(&r0p[c]);
        float2 q10 = *reinterpret_cast<const float2*>(&r1p[c]);
        float2 q01 = *reinterpret_cast<const float2*>(&r0p[c + 8]);
        float2 q11 = *reinterpret_cast<const float2*>(&r1p[c + 8]);
        QAh[e] = make_uint4(pkh2(q00.x, q00.y), pkh2(q10.x, q10.y),
                            pkh2(q01.x, q01.y), pkh2(q11.x, q11.y));
        QAl[e] = make_uint4(pkh2(f16lo(q00.x), f16lo(q00.y)),
                            pkh2(f16lo(q10.x), f16lo(q10.y)),
                            pkh2(f16lo(q01.x), f16lo(q01.y)),
                            pkh2(f16lo(q11.x), f16lo(q11.y)));
    }

    float o[2][8][4];
    #pragma unroll
    for (int m = 0; m < 2; m++)
        #pragma unroll
        for (int n = 0; n < 8; n++)
            #pragma unroll
            for (int i = 0; i < 4; i++) o[m][n][i] = 0.0f;
    float mr[2][2], lr[2][2];
    #pragma unroll
    for (int m = 0; m < 2; m++) {
        mr[m][0] = mr[m][1] = -1e30f;
        lr[m][0] = lr[m][1] = 0.0f;
    }

    float4 kfa[2], kfb[2];   // K prefetch only (V loads at staging time)

    auto prefetch_k = [&](int t) {
        const int t0 = split * KEYS_PER_SPLIT + t * KTILE;
        kfa[0] = *reinterpret_cast<const float4*>(&kb[(long)(t0 + kkey0) * HDIM + kc0 * 8]);
        kfb[0] = *reinterpret_cast<const float4*>(&kb[(long)(t0 + kkey0) * HDIM + kc0 * 8 + 4]);
        kfa[1] = *reinterpret_cast<const float4*>(&kb[(long)(t0 + kkey1) * HDIM + kc1 * 8]);
        kfb[1] = *reinterpret_cast<const float4*>(&kb[(long)(t0 + kkey1) * HDIM + kc1 * 8 + 4]);
    };
    auto write_tile = [&](int t) {
        #pragma unroll
        for (int p = 0; p < 2; p++) {
            const int key = p ? kkey1 : kkey0;
            const int c   = p ? kc1 : kc0;
            float4 fa = kfa[p], fb = kfb[p];
            float f[8] = {fa.x, fa.y, fa.z, fa.w, fb.x, fb.y, fb.z, fb.w};
            const int kap = c >> 1, cb = c & 1;
            #pragma unroll
            for (int t2 = 0; t2 < 4; t2++) {
                const int idx = key * KVSTRU2 + kap * 4 + t2;
                reinterpret_cast<uint32*>(&Kh[idx])[cb] = pkh2(f[2 * t2], f[2 * t2 + 1]);
                reinterpret_cast<uint32*>(&Kl[idx])[cb] =
                    pkh2(f16lo(f[2 * t2]), f16lo(f[2 * t2 + 1]));
            }
        }
        {
            const int t0 = split * KEYS_PER_SPLIT + t * KTILE;
            float4 va0 = *reinterpret_cast<const float4*>(&vb[(long)(t0 + 2 * vk2) * HDIM + vh8]);
            float4 va1 = *reinterpret_cast<const float4*>(&vb[(long)(t0 + 2 * vk2) * HDIM + vh8 + 4]);
            float4 vb0 = *reinterpret_cast<const float4*>(&vb[(long)(t0 + 2 * vk2 + 1) * HDIM + vh8]);
            float4 vb1 = *reinterpret_cast<const float4*>(&vb[(long)(t0 + 2 * vk2 + 1) * HDIM + vh8 + 4]);
            float va[8] = {va0.x, va0.y, va0.z, va0.w, va1.x, va1.y, va1.z, va1.w};
            float vv[8] = {vb0.x, vb0.y, vb0.z, vb0.w, vb1.x, vb1.y, vb1.z, vb1.w};
            const int kap = vk2 >> 3, r = vk2 & 7;
            const int cb = r >> 2, tt = r & 3;
            #pragma unroll
            for (int j = 0; j < 8; j++) {
                const int h = vh8 + j;
                reinterpret_cast<uint32*>(&Vh[h * KVSTRU2 + kap * 4 + tt])[cb] =
                    pkh2(va[j], vv[j]);
            }
        }
    };

    prefetch_k(0);

    #pragma unroll 1
    for (int t = 0; t < NT; t++) {
        __syncthreads();
        write_tile(t);
        __syncthreads();
        if (t + 1 < NT) prefetch_k(t + 1);

        // ---- QK: S = Q K^T, 3-term fp16 split ----
        float s[2][4][4];
        #pragma unroll
        for (int m = 0; m < 2; m++)
            #pragma unroll
            for (int n = 0; n < 4; n++)
                #pragma unroll
                for (int i = 0; i < 4; i++) s[m][n][i] = 0.0f;

        #pragma unroll
        for (int kap = 0; kap < 4; kap++) {
            uint4 qh[2], ql[2];
            #pragma unroll
            for (int m = 0; m < 2; m++) {
                const int idx = (w * 2 + m) * 128 + kap * 32 + g * 4 + tg;
                qh[m] = QAh[idx];
                ql[m] = QAl[idx];
            }
            #pragma unroll
            for (int n = 0; n < 4; n++) {
                const int kidx = (8 * n + g) * KVSTRU2 + kap * 4 + tg;
                uint2 kh = Kh[kidx];
                uint2 kl = Kl[kidx];
                #pragma unroll
                for (int m = 0; m < 2; m++) {
                    mma_f16(s[m][n][0], s[m][n][1], s[m][n][2], s[m][n][3],
                            qh[m].x, qh[m].y, qh[m].z, qh[m].w, kh.x, kh.y);
                    mma_f16(s[m][n][0], s[m][n][1], s[m][n][2], s[m][n][3],
                            ql[m].x, ql[m].y, ql[m].z, ql[m].w, kh.x, kh.y);
                    mma_f16(s[m][n][0], s[m][n][1], s[m][n][2], s[m][n][3],
                            qh[m].x, qh[m].y, qh[m].z, qh[m].w, kl.x, kl.y);
                }
            }
        }

        // ---- online softmax ----
        #pragma unroll
        for (int m = 0; m < 2; m++) {
            const int mb = w * 2 + m;
            float mxA = -1e30f, mxB = -1e30f;
            #pragma unroll
            for (int n = 0; n < 4; n++) {
                mxA = fmaxf(mxA, fmaxf(s[m][n][0], s[m][n][1]));
                mxB = fmaxf(mxB, fmaxf(s[m][n][2], s[m][n][3]));
            }
            mxA = fmaxf(mxA, __shfl_xor_sync(0xffffffffu, mxA, 1));
            mxA = fmaxf(mxA, __shfl_xor_sync(0xffffffffu, mxA, 2));
            mxB = fmaxf(mxB, __shfl_xor_sync(0xffffffffu, mxB, 1));
            mxB = fmaxf(mxB, __shfl_xor_sync(0xffffffffu, mxB, 2));

            const float nmA = fmaxf(mr[m][0], mxA);
            const float nmB = fmaxf(mr[m][1], mxB);
            const float alA = __expf(mr[m][0] - nmA);
            const float alB = __expf(mr[m][1] - nmB);
            mr[m][0] = nmA; mr[m][1] = nmB;

            float lsA = 0.0f, lsB = 0.0f;
            #pragma unroll
            for (int n = 0; n < 4; n++) {
                float p0 = __expf(s[m][n][0] - nmA);
                float p1 = __expf(s[m][n][1] - nmA);
                float p2 = __expf(s[m][n][2] - nmB);
                float p3 = __expf(s[m][n][3] - nmB);
                lsA += p0 + p1;
                lsB += p2 + p3;
                P2h[mb * 192 + (4 * n + tg) * PSTRU2 + g] =
                    make_uint2(pkh2(p0, p1), pkh2(p2, p3));
            }
            lsA += __shfl_xor_sync(0xffffffffu, lsA, 1);
            lsA += __shfl_xor_sync(0xffffffffu, lsA, 2);
            lsB += __shfl_xor_sync(0xffffffffu, lsB, 1);
            lsB += __shfl_xor_sync(0xffffffffu, lsB, 2);
            lr[m][0] = lr[m][0] * alA + lsA;
            lr[m][1] = lr[m][1] * alB + lsB;

            if (__any_sync(0xffffffffu, (alA != 1.0f) || (alB != 1.0f))) {
                #pragma unroll
                for (int n = 0; n < 8; n++) {
                    o[m][n][0] *= alA; o[m][n][1] *= alA;
                    o[m][n][2] *= alB; o[m][n][3] *= alB;
                }
            }
        }
        __syncwarp();

        // ---- PV: O += P V (1x fp16) ----
        #pragma unroll
        for (int kap = 0; kap < 2; kap++) {
            uint2 pa[2], pb[2];
            #pragma unroll
            for (int m = 0; m < 2; m++) {
                const int mb = w * 2 + m;
                pa[m] = P2h[mb * 192 + (8 * kap + tg) * PSTRU2 + g];
                pb[m] = P2h[mb * 192 + (8 * kap + tg + 4) * PSTRU2 + g];
            }
            #pragma unroll
            for (int n = 0; n < 8; n++) {
                uint2 vp = Vh[(8 * n + g) * KVSTRU2 + kap * 4 + tg];
                #pragma unroll
                for (int m = 0; m < 2; m++) {
                    mma_f16(o[m][n][0], o[m][n][1], o[m][n][2], o[m][n][3],
                            pa[m].x, pa[m].y, pb[m].x, pb[m].y, vp.x, vp.y);
                }
            }
        }
    }

    // ---- epilogue ----
    #pragma unroll
    for (int m = 0; m < 2; m++) {
        const long rowA = (long)b * TSEQ + q0 + w * 32 + m * 16 + g;
        const long rowB = rowA + 8;
        #pragma unroll
        for (int n = 0; n < 8; n++) {
            const int c = n * 8 + 2 * tg;
            *reinterpret_cast<float2*>(&g_pacc[split][rowA][c]) =
                make_float2(o[m][n][0], o[m][n][1]);
            *reinterpret_cast<float2*>(&g_pacc[split][rowB][c]) =
                make_float2(o[m][n][2], o[m][n][3]);
        }
        if (tg == 0) {
            g_pm[split][rowA] = mr[m][0];
            g_pl[split][rowA] = lr[m][0];
            g_pm[split][rowB] = mr[m][1];
            g_pl[split][rowB] = lr[m][1];
        }
    }
}

// ---------------------------------------------------------------------------
// Combine split-KV partials.
// ---------------------------------------------------------------------------
__global__ __launch_bounds__(128) void combine_kernel(float* __restrict__ out)
{
    const long row = (long)blockIdx.x * 128 + threadIdx.x;

    float m[NSPLIT], w[NSPLIT];
    float M = -1e30f;
    #pragma unroll
    for (int i = 0; i < NSPLIT; i++) {
        m[i] = g_pm[i][row];
        M = fmaxf(M, m[i]);
    }
    float L = 0.0f;
    #pragma unroll
    for (int i = 0; i < NSPLIT; i++) {
        w[i] = __expf(m[i] - M);
        L += w[i] * g_pl[i][row];
    }
    const float inv = 1.0f / L;

    float* __restrict__ orow = &out[row * HDIM];
    #pragma unroll
    for (int h = 0; h < HDIM; h += 4) {
        float4 a = make_float4(0.f, 0.f, 0.f, 0.f);
        #pragma unroll
        for (int i = 0; i < NSPLIT; i++) {
            float4 p = *reinterpret_cast<const float4*>(&g_pacc[i][row][h]);
            a.x += w[i] * p.x;
            a.y += w[i] * p.y;
            a.z += w[i] * p.z;
            a.w += w[i] * p.w;
        }
        a.x *= inv; a.y *= inv; a.z *= inv; a.w *= inv;
        *reinterpret_cast<float4*>(&orow[h]) = a;
    }
}

// ---------------------------------------------------------------------------
extern "C" void kernel_launch(void* const* d_in, const int* in_sizes, int n_in,
                              void* d_out, int out_size)
{
    const float* x  = (const float*)d_in[0];
    const float* Wq = (const float*)d_in[1];
    const float* Wk = (const float*)d_in[2];
    const float* Wv = (const float*)d_in[3];
    float* out = (float*)d_out;

    transpose_w_kernel<<<dim3(64, 3), 256>>>(Wq, Wk, Wv);

    proj_mma_kernel<<<dim3(BT_TOTAL / 128, 3), 128>>>(x);

    const int smem_bytes = 65536;
    static bool attr_set = false;
    if (!attr_set) {
        cudaFuncSetAttribute(attn_mma_kernel,
                             cudaFuncAttributeMaxDynamicSharedMemorySize, smem_bytes);
        attr_set = true;
    }
    dim3 ag(TSEQ / QTILE, BATCH, NSPLIT);
    attn_mma_kernel<<<ag, 128, smem_bytes>>>();

    combine_kernel<<<BT_TOTAL / 128, 128>>>(out);
}